// round 4
// baseline (speedup 1.0000x reference)
#include <cuda_runtime.h>
#include <math.h>

#define BB 8
#define CIN 128
#define COUT 128
#define HH 64
#define WW 64
#define KHW 3
#define KK 9
#define PP 4096            // Ho*Wo
#define MK 1152            // Cin*K

// 151 MB scratch: cols[b][c*K+k][p]
__device__ float g_cols[(size_t)BB * MK * PP];

__global__ __launch_bounds__(256) void im2col_kernel(
    const float* __restrict__ input,
    const float* __restrict__ offset,
    const float* __restrict__ mask)
{
    int gid = blockIdx.x * blockDim.x + threadIdx.x;
    if (gid >= BB * KK * PP) return;
    int p = gid & (PP - 1);
    int t = gid >> 12;           // PP = 2^12
    int k = t % KK;
    int b = t / KK;
    int y = p >> 6;
    int x = p & 63;

    float offy = offset[((size_t)b * 2 * KK + 2 * k) * PP + p];
    float offx = offset[((size_t)b * 2 * KK + 2 * k + 1) * PP + p];
    float mval = mask[((size_t)b * KK + k) * PP + p];

    float py = offy + (float)(y - 1 + k / KHW);
    float px = offx + (float)(x - 1 + k % KHW);

    float y0f = floorf(py), x0f = floorf(px);
    float ly = py - y0f, lx = px - x0f;
    int y0 = (int)y0f, x0 = (int)x0f;
    int y1 = y0 + 1, x1 = x0 + 1;

    bool vy0 = (y0 >= 0) & (y0 < HH);
    bool vy1 = (y1 >= 0) & (y1 < HH);
    bool vx0 = (x0 >= 0) & (x0 < WW);
    bool vx1 = (x1 >= 0) & (x1 < WW);

    int cy0 = min(max(y0, 0), HH - 1), cy1 = min(max(y1, 0), HH - 1);
    int cx0 = min(max(x0, 0), WW - 1), cx1 = min(max(x1, 0), WW - 1);
    int o00 = cy0 * WW + cx0, o01 = cy0 * WW + cx1;
    int o10 = cy1 * WW + cx0, o11 = cy1 * WW + cx1;

    float w00 = (1.f - ly) * (1.f - lx) * ((vy0 & vx0) ? 1.f : 0.f) * mval;
    float w01 = (1.f - ly) * lx         * ((vy0 & vx1) ? 1.f : 0.f) * mval;
    float w10 = ly * (1.f - lx)         * ((vy1 & vx0) ? 1.f : 0.f) * mval;
    float w11 = ly * lx                 * ((vy1 & vx1) ? 1.f : 0.f) * mval;

    const float* inb = input + (size_t)b * CIN * HH * WW;
    float* outp = g_cols + ((size_t)b * MK + k) * PP + p;

    #pragma unroll 4
    for (int c = 0; c < CIN; c++) {
        const float* ic = inb + (size_t)c * HH * WW;
        float v = w00 * __ldg(ic + o00) + w01 * __ldg(ic + o01)
                + w10 * __ldg(ic + o10) + w11 * __ldg(ic + o11);
        outp[(size_t)c * KK * PP] = v;
    }
}

// SGEMM: out[b][co][p] = sum_m W2[co][m] * cols[b][m][p] + bias[co]
// M=128 (=BM, single block row), N=4096 per batch, K=1152.
__global__ __launch_bounds__(256) void gemm_kernel(
    const float* __restrict__ Wt,     // [128][1152]
    const float* __restrict__ bias,   // [128]
    float* __restrict__ out)          // [B][128][4096]
{
    __shared__ float As[8][128];
    __shared__ float Bs[8][128];

    int b  = blockIdx.z;
    int n0 = blockIdx.x * 128;
    const float* Bmat = g_cols + (size_t)b * MK * PP;

    int tid = threadIdx.x;
    int tx = tid & 15;     // 0..15  -> N microtile
    int ty = tid >> 4;     // 0..15  -> M microtile

    // A-tile load: transposed store As[kc][m]
    int ar = tid >> 1;            // 0..127 (m)
    int ac = (tid & 1) * 4;       // 0 or 4 (k)
    // B-tile load
    int br = tid >> 5;            // 0..7   (k)
    int bc = (tid & 31) * 4;      // 0..124 (n)

    float acc[8][8];
    #pragma unroll
    for (int i = 0; i < 8; i++)
        #pragma unroll
        for (int j = 0; j < 8; j++) acc[i][j] = 0.f;

    for (int kt = 0; kt < MK; kt += 8) {
        float4 a4 = *reinterpret_cast<const float4*>(Wt + (size_t)ar * MK + kt + ac);
        As[ac + 0][ar] = a4.x;
        As[ac + 1][ar] = a4.y;
        As[ac + 2][ar] = a4.z;
        As[ac + 3][ar] = a4.w;

        float4 b4 = *reinterpret_cast<const float4*>(Bmat + (size_t)(kt + br) * PP + n0 + bc);
        *reinterpret_cast<float4*>(&Bs[br][bc]) = b4;

        __syncthreads();

        #pragma unroll
        for (int kk = 0; kk < 8; kk++) {
            float ra[8], rb[8];
            #pragma unroll
            for (int i = 0; i < 8; i++) ra[i] = As[kk][ty * 8 + i];
            #pragma unroll
            for (int j = 0; j < 8; j++) rb[j] = Bs[kk][tx * 8 + j];
            #pragma unroll
            for (int i = 0; i < 8; i++)
                #pragma unroll
                for (int j = 0; j < 8; j++)
                    acc[i][j] += ra[i] * rb[j];
        }
        __syncthreads();
    }

    float* outb = out + (size_t)b * COUT * PP;
    #pragma unroll
    for (int i = 0; i < 8; i++) {
        int row = ty * 8 + i;
        float bv = bias[row];
        float4 v0 = make_float4(acc[i][0] + bv, acc[i][1] + bv, acc[i][2] + bv, acc[i][3] + bv);
        float4 v1 = make_float4(acc[i][4] + bv, acc[i][5] + bv, acc[i][6] + bv, acc[i][7] + bv);
        float* dst = outb + (size_t)row * PP + n0 + tx * 8;
        *reinterpret_cast<float4*>(dst)     = v0;
        *reinterpret_cast<float4*>(dst + 4) = v1;
    }
}

extern "C" void kernel_launch(void* const* d_in, const int* in_sizes, int n_in,
                              void* d_out, int out_size)
{
    const float* input  = (const float*)d_in[0];
    const float* offset = (const float*)d_in[1];
    const float* mask   = (const float*)d_in[2];
    const float* weight = (const float*)d_in[3];
    const float* bias   = (const float*)d_in[4];
    float* out = (float*)d_out;

    int total = BB * KK * PP;                 // 294912
    im2col_kernel<<<(total + 255) / 256, 256>>>(input, offset, mask);

    dim3 grid(PP / 128, 1, BB);               // (32, 1, 8)
    gemm_kernel<<<grid, 256>>>(weight, bias, out);
}

// round 5
// speedup vs baseline: 1.7744x; 1.7744x over previous
#include <cuda_runtime.h>
#include <math.h>
#include <stdint.h>

#define BB 8
#define CIN 128
#define COUT 128
#define HH 64
#define WW 64
#define KHW 3
#define KK 9
#define PP 4096            // Ho*Wo
#define MK 1152            // Cin*K

// 151 MB scratch: cols[b][c*K+k][p]
__device__ float g_cols[(size_t)BB * MK * PP];

__global__ __launch_bounds__(256) void im2col_kernel(
    const float* __restrict__ input,
    const float* __restrict__ offset,
    const float* __restrict__ mask)
{
    int gid = blockIdx.x * blockDim.x + threadIdx.x;
    if (gid >= BB * KK * PP) return;
    int p = gid & (PP - 1);
    int t = gid >> 12;           // PP = 2^12
    int k = t % KK;
    int b = t / KK;
    int y = p >> 6;
    int x = p & 63;

    float offy = offset[((size_t)b * 2 * KK + 2 * k) * PP + p];
    float offx = offset[((size_t)b * 2 * KK + 2 * k + 1) * PP + p];
    float mval = mask[((size_t)b * KK + k) * PP + p];

    float py = offy + (float)(y - 1 + k / KHW);
    float px = offx + (float)(x - 1 + k % KHW);

    float y0f = floorf(py), x0f = floorf(px);
    float ly = py - y0f, lx = px - x0f;
    int y0 = (int)y0f, x0 = (int)x0f;
    int y1 = y0 + 1, x1 = x0 + 1;

    bool vy0 = (y0 >= 0) & (y0 < HH);
    bool vy1 = (y1 >= 0) & (y1 < HH);
    bool vx0 = (x0 >= 0) & (x0 < WW);
    bool vx1 = (x1 >= 0) & (x1 < WW);

    int cy0 = min(max(y0, 0), HH - 1), cy1 = min(max(y1, 0), HH - 1);
    int cx0 = min(max(x0, 0), WW - 1), cx1 = min(max(x1, 0), WW - 1);
    int o00 = cy0 * WW + cx0, o01 = cy0 * WW + cx1;
    int o10 = cy1 * WW + cx0, o11 = cy1 * WW + cx1;

    float w00 = (1.f - ly) * (1.f - lx) * ((vy0 & vx0) ? 1.f : 0.f) * mval;
    float w01 = (1.f - ly) * lx         * ((vy0 & vx1) ? 1.f : 0.f) * mval;
    float w10 = ly * (1.f - lx)         * ((vy1 & vx0) ? 1.f : 0.f) * mval;
    float w11 = ly * lx                 * ((vy1 & vx1) ? 1.f : 0.f) * mval;

    const float* inb = input + (size_t)b * CIN * HH * WW;
    float* outp = g_cols + ((size_t)b * MK + k) * PP + p;

    #pragma unroll 4
    for (int c = 0; c < CIN; c++) {
        const float* ic = inb + (size_t)c * HH * WW;
        float v = w00 * __ldg(ic + o00) + w01 * __ldg(ic + o01)
                + w10 * __ldg(ic + o10) + w11 * __ldg(ic + o11);
        outp[(size_t)c * KK * PP] = v;
    }
}

// ---------------------------------------------------------------------------
// TF32 tensor-core GEMM: out[b][co][p] = sum_m W[co][m] * cols[b][m][p] + bias
// M=128 (co), N=4096 per batch (p), K=1152 (m).
// Block tile 128x128x16, 256 threads = 8 warps (2 along M x 4 along N),
// warp tile 64x32, mma.m16n8k8 frags 4x4. Double-buffered smem.
// ---------------------------------------------------------------------------

#define BK 16
#define LDA 136   // smem row stride in words (conflict-free + 16B aligned)

__device__ __forceinline__ uint32_t f2tf32(float f) {
    uint32_t r;
    asm("cvt.rna.tf32.f32 %0, %1;" : "=r"(r) : "f"(f));
    return r;
}

__global__ __launch_bounds__(256) void gemm_tf32_kernel(
    const float* __restrict__ Wt,     // [128][1152]
    const float* __restrict__ bias,   // [128]
    float* __restrict__ out)          // [B][128][4096]
{
    __shared__ uint32_t As[2][BK][LDA];   // [k][co]
    __shared__ uint32_t Bs[2][BK][LDA];   // [k][n]

    const int b  = blockIdx.z;
    const int n0 = blockIdx.x * 128;
    const float* Bmat = g_cols + (size_t)b * MK * PP;

    const int tid  = threadIdx.x;
    const int wid  = tid >> 5;
    const int lane = tid & 31;
    const int wm = wid & 1;          // 0..1 -> 64-row slab
    const int wn = wid >> 1;         // 0..3 -> 32-col slab
    const int m_base = wm * 64;
    const int n_base = wn * 32;
    const int qr = lane >> 2;        // 0..7
    const int qc = lane & 3;         // 0..3

    // Global-load mapping
    const int a_co = tid & 127;          // A: row of W
    const int a_kh = tid >> 7;           // 0..1 -> k offsets {0,4} within 8
    const int b_n4 = (tid & 31) * 4;     // B: 4-float group in N
    const int b_kc = tid >> 5;           // 0..7 (plus +8)

    float4 ra0, ra1, rb0, rb1;

    float acc[4][4][4];
    #pragma unroll
    for (int mi = 0; mi < 4; mi++)
        #pragma unroll
        for (int ni = 0; ni < 4; ni++)
            #pragma unroll
            for (int c = 0; c < 4; c++) acc[mi][ni][c] = 0.f;

    // ---- prologue: stage 0 ----
    {
        const float* ap = Wt + (size_t)a_co * MK + a_kh * 8;
        ra0 = *reinterpret_cast<const float4*>(ap);
        ra1 = *reinterpret_cast<const float4*>(ap + 4);
        const float* bp = Bmat + (size_t)b_kc * PP + n0 + b_n4;
        rb0 = *reinterpret_cast<const float4*>(bp);
        rb1 = *reinterpret_cast<const float4*>(bp + (size_t)8 * PP);
    }
    {
        int k8 = a_kh * 8;
        As[0][k8 + 0][a_co] = f2tf32(ra0.x);
        As[0][k8 + 1][a_co] = f2tf32(ra0.y);
        As[0][k8 + 2][a_co] = f2tf32(ra0.z);
        As[0][k8 + 3][a_co] = f2tf32(ra0.w);
        As[0][k8 + 4][a_co] = f2tf32(ra1.x);
        As[0][k8 + 5][a_co] = f2tf32(ra1.y);
        As[0][k8 + 6][a_co] = f2tf32(ra1.z);
        As[0][k8 + 7][a_co] = f2tf32(ra1.w);
        uint4 v0 = make_uint4(f2tf32(rb0.x), f2tf32(rb0.y), f2tf32(rb0.z), f2tf32(rb0.w));
        uint4 v1 = make_uint4(f2tf32(rb1.x), f2tf32(rb1.y), f2tf32(rb1.z), f2tf32(rb1.w));
        *reinterpret_cast<uint4*>(&Bs[0][b_kc][b_n4])     = v0;
        *reinterpret_cast<uint4*>(&Bs[0][b_kc + 8][b_n4]) = v1;
    }
    __syncthreads();

    int buf = 0;
    for (int kt = BK; kt <= MK; kt += BK) {
        // prefetch next stage into registers
        if (kt < MK) {
            const float* ap = Wt + (size_t)a_co * MK + kt + a_kh * 8;
            ra0 = *reinterpret_cast<const float4*>(ap);
            ra1 = *reinterpret_cast<const float4*>(ap + 4);
            const float* bp = Bmat + (size_t)(kt + b_kc) * PP + n0 + b_n4;
            rb0 = *reinterpret_cast<const float4*>(bp);
            rb1 = *reinterpret_cast<const float4*>(bp + (size_t)8 * PP);
        }

        // compute current buffer: 2 k8-steps
        #pragma unroll
        for (int ks = 0; ks < 2; ks++) {
            const int k0 = ks * 8;
            uint32_t afr[4][4];
            uint32_t bfr[4][2];
            #pragma unroll
            for (int mi = 0; mi < 4; mi++) {
                int r = m_base + mi * 16 + qr;
                afr[mi][0] = As[buf][k0 + qc][r];
                afr[mi][1] = As[buf][k0 + qc][r + 8];
                afr[mi][2] = As[buf][k0 + qc + 4][r];
                afr[mi][3] = As[buf][k0 + qc + 4][r + 8];
            }
            #pragma unroll
            for (int ni = 0; ni < 4; ni++) {
                int c = n_base + ni * 8 + qr;
                bfr[ni][0] = Bs[buf][k0 + qc][c];
                bfr[ni][1] = Bs[buf][k0 + qc + 4][c];
            }
            #pragma unroll
            for (int mi = 0; mi < 4; mi++)
                #pragma unroll
                for (int ni = 0; ni < 4; ni++) {
                    asm volatile(
                        "mma.sync.aligned.m16n8k8.row.col.f32.tf32.tf32.f32 "
                        "{%0,%1,%2,%3}, {%4,%5,%6,%7}, {%8,%9}, {%0,%1,%2,%3};\n"
                        : "+f"(acc[mi][ni][0]), "+f"(acc[mi][ni][1]),
                          "+f"(acc[mi][ni][2]), "+f"(acc[mi][ni][3])
                        : "r"(afr[mi][0]), "r"(afr[mi][1]),
                          "r"(afr[mi][2]), "r"(afr[mi][3]),
                          "r"(bfr[ni][0]), "r"(bfr[ni][1]));
                }
        }

        // store prefetched stage into other buffer
        if (kt < MK) {
            int nb = buf ^ 1;
            int k8 = a_kh * 8;
            As[nb][k8 + 0][a_co] = f2tf32(ra0.x);
            As[nb][k8 + 1][a_co] = f2tf32(ra0.y);
            As[nb][k8 + 2][a_co] = f2tf32(ra0.z);
            As[nb][k8 + 3][a_co] = f2tf32(ra0.w);
            As[nb][k8 + 4][a_co] = f2tf32(ra1.x);
            As[nb][k8 + 5][a_co] = f2tf32(ra1.y);
            As[nb][k8 + 6][a_co] = f2tf32(ra1.z);
            As[nb][k8 + 7][a_co] = f2tf32(ra1.w);
            uint4 v0 = make_uint4(f2tf32(rb0.x), f2tf32(rb0.y), f2tf32(rb0.z), f2tf32(rb0.w));
            uint4 v1 = make_uint4(f2tf32(rb1.x), f2tf32(rb1.y), f2tf32(rb1.z), f2tf32(rb1.w));
            *reinterpret_cast<uint4*>(&Bs[nb][b_kc][b_n4])     = v0;
            *reinterpret_cast<uint4*>(&Bs[nb][b_kc + 8][b_n4]) = v1;
        }
        __syncthreads();
        buf ^= 1;
    }

    // epilogue: c0/c1 -> row r, cols c,c+1 ; c2/c3 -> row r+8
    float* outb = out + (size_t)b * COUT * PP;
    const int cr = lane >> 2;          // 0..7
    const int cc = (lane & 3) * 2;     // 0,2,4,6
    #pragma unroll
    for (int mi = 0; mi < 4; mi++) {
        int r0 = m_base + mi * 16 + cr;
        float bv0 = bias[r0];
        float bv1 = bias[r0 + 8];
        #pragma unroll
        for (int ni = 0; ni < 4; ni++) {
            int col = n0 + n_base + ni * 8 + cc;
            float2 v0 = make_float2(acc[mi][ni][0] + bv0, acc[mi][ni][1] + bv0);
            float2 v1 = make_float2(acc[mi][ni][2] + bv1, acc[mi][ni][3] + bv1);
            *reinterpret_cast<float2*>(outb + (size_t)r0 * PP + col)       = v0;
            *reinterpret_cast<float2*>(outb + (size_t)(r0 + 8) * PP + col) = v1;
        }
    }
}

extern "C" void kernel_launch(void* const* d_in, const int* in_sizes, int n_in,
                              void* d_out, int out_size)
{
    const float* input  = (const float*)d_in[0];
    const float* offset = (const float*)d_in[1];
    const float* mask   = (const float*)d_in[2];
    const float* weight = (const float*)d_in[3];
    const float* bias   = (const float*)d_in[4];
    float* out = (float*)d_out;

    int total = BB * KK * PP;                 // 294912
    im2col_kernel<<<(total + 255) / 256, 256>>>(input, offset, mask);

    dim3 grid(PP / 128, 1, BB);               // (32, 1, 8)
    gemm_tf32_kernel<<<grid, 256>>>(weight, bias, out);
}

// round 6
// speedup vs baseline: 2.4214x; 1.3646x over previous
#include <cuda_runtime.h>
#include <math.h>
#include <stdint.h>

#define BB 8
#define CIN 128
#define COUT 128
#define HH 64
#define WW 64
#define KHW 3
#define KK 9
#define PP 4096            // Ho*Wo
#define MK 1152            // Cin*K

// 151 MB scratch: cols[b][c*K+k][p]  (stored pre-rounded to tf32 bit pattern)
__device__ float g_cols[(size_t)BB * MK * PP];
// W transposed + tf32-rounded: g_wt[k][co]
__device__ float g_wt[(size_t)MK * COUT];

__device__ __forceinline__ uint32_t f2tf32(float f) {
    uint32_t r;
    asm("cvt.rna.tf32.f32 %0, %1;" : "=r"(r) : "f"(f));
    return r;
}

__global__ __launch_bounds__(256) void im2col_kernel(
    const float* __restrict__ input,
    const float* __restrict__ offset,
    const float* __restrict__ mask)
{
    int gid = blockIdx.x * blockDim.x + threadIdx.x;
    if (gid >= BB * KK * PP) return;
    int p = gid & (PP - 1);
    int t = gid >> 12;           // PP = 2^12
    int k = t % KK;
    int b = t / KK;
    int y = p >> 6;
    int x = p & 63;

    float offy = offset[((size_t)b * 2 * KK + 2 * k) * PP + p];
    float offx = offset[((size_t)b * 2 * KK + 2 * k + 1) * PP + p];
    float mval = mask[((size_t)b * KK + k) * PP + p];

    float py = offy + (float)(y - 1 + k / KHW);
    float px = offx + (float)(x - 1 + k % KHW);

    float y0f = floorf(py), x0f = floorf(px);
    float ly = py - y0f, lx = px - x0f;
    int y0 = (int)y0f, x0 = (int)x0f;
    int y1 = y0 + 1, x1 = x0 + 1;

    bool vy0 = (y0 >= 0) & (y0 < HH);
    bool vy1 = (y1 >= 0) & (y1 < HH);
    bool vx0 = (x0 >= 0) & (x0 < WW);
    bool vx1 = (x1 >= 0) & (x1 < WW);

    int cy0 = min(max(y0, 0), HH - 1), cy1 = min(max(y1, 0), HH - 1);
    int cx0 = min(max(x0, 0), WW - 1), cx1 = min(max(x1, 0), WW - 1);
    int o00 = cy0 * WW + cx0, o01 = cy0 * WW + cx1;
    int o10 = cy1 * WW + cx0, o11 = cy1 * WW + cx1;

    float w00 = (1.f - ly) * (1.f - lx) * ((vy0 & vx0) ? 1.f : 0.f) * mval;
    float w01 = (1.f - ly) * lx         * ((vy0 & vx1) ? 1.f : 0.f) * mval;
    float w10 = ly * (1.f - lx)         * ((vy1 & vx0) ? 1.f : 0.f) * mval;
    float w11 = ly * lx                 * ((vy1 & vx1) ? 1.f : 0.f) * mval;

    const float* inb = input + (size_t)b * CIN * HH * WW;
    float* outp = g_cols + ((size_t)b * MK + k) * PP + p;

    #pragma unroll 4
    for (int c = 0; c < CIN; c++) {
        const float* ic = inb + (size_t)c * HH * WW;
        float v = w00 * __ldg(ic + o00) + w01 * __ldg(ic + o01)
                + w10 * __ldg(ic + o10) + w11 * __ldg(ic + o11);
        outp[(size_t)c * KK * PP] = __uint_as_float(f2tf32(v));
    }
}

// Transpose + round W: g_wt[k][co] = tf32(W[co][k])
__global__ __launch_bounds__(256) void wprep_kernel(const float* __restrict__ Wt)
{
    int idx = blockIdx.x * blockDim.x + threadIdx.x;
    if (idx >= MK * COUT) return;
    int k  = idx >> 7;
    int co = idx & 127;
    g_wt[idx] = __uint_as_float(f2tf32(Wt[(size_t)co * MK + k]));
}

// ---------------------------------------------------------------------------
// TF32 tensor-core GEMM, cp.async 3-stage pipeline.
// out[b][co][p] = sum_m W[co][m] * cols[b][m][p] + bias[co]
// Block tile 128x128x16, 256 threads = 8 warps (2 M x 4 N), warp tile 64x32.
// ---------------------------------------------------------------------------

#define BK 16
#define LDA 136            // smem row stride (words): conflict-free + 16B-aligned
#define NSTG 3
#define STAGE_WORDS (BK * LDA)
#define SMEM_BYTES (2 * NSTG * STAGE_WORDS * 4)   // 52224

__device__ __forceinline__ void cp16(uint32_t dst, const void* src) {
    asm volatile("cp.async.cg.shared.global [%0], [%1], 16;\n"
                 :: "r"(dst), "l"(src));
}

__global__ __launch_bounds__(256) void gemm_tf32_kernel(
    const float* __restrict__ bias,
    float* __restrict__ out)          // [B][128][4096]
{
    extern __shared__ uint32_t smem[];
    uint32_t* As0 = smem;                       // [NSTG][BK][LDA]
    uint32_t* Bs0 = smem + NSTG * STAGE_WORDS;  // [NSTG][BK][LDA]

    const int b  = blockIdx.z;
    const int n0 = blockIdx.x * 128;
    const float* Bmat = g_cols + (size_t)b * MK * PP;

    const int tid  = threadIdx.x;
    const int wid  = tid >> 5;
    const int lane = tid & 31;
    const int wm = wid & 1;
    const int wn = wid >> 1;
    const int m_base = wm * 64;
    const int n_base = wn * 32;
    const int qr = lane >> 2;
    const int qc = lane & 3;

    // cp.async mapping: each thread moves 2 float4 per tile (rows r0, r0+8)
    const int r0 = tid >> 5;          // 0..7
    const int c0 = (tid & 31) * 4;    // 0..124

    uint32_t smem_u32 = (uint32_t)__cvta_generic_to_shared(smem);
    const uint32_t a_base = smem_u32;
    const uint32_t b_base = smem_u32 + NSTG * STAGE_WORDS * 4;

    float acc[4][4][4];
    #pragma unroll
    for (int mi = 0; mi < 4; mi++)
        #pragma unroll
        for (int ni = 0; ni < 4; ni++)
            #pragma unroll
            for (int c = 0; c < 4; c++) acc[mi][ni][c] = 0.f;

    const int NK = MK / BK;   // 72

    // stage issue
    auto issue = [&](int s, int kt) {
        uint32_t ad = a_base + (uint32_t)(s * STAGE_WORDS + r0 * LDA + c0) * 4;
        const float* asrc = g_wt + (size_t)(kt + r0) * COUT + c0;
        cp16(ad,                asrc);
        cp16(ad + 8 * LDA * 4,  asrc + (size_t)8 * COUT);
        uint32_t bd = b_base + (uint32_t)(s * STAGE_WORDS + r0 * LDA + c0) * 4;
        const float* bsrc = Bmat + (size_t)(kt + r0) * PP + n0 + c0;
        cp16(bd,                bsrc);
        cp16(bd + 8 * LDA * 4,  bsrc + (size_t)8 * PP);
    };

    issue(0, 0);
    asm volatile("cp.async.commit_group;\n");
    issue(1, BK);
    asm volatile("cp.async.commit_group;\n");

    for (int i = 0; i < NK; i++) {
        if (i + 2 < NK) issue((i + 2) % NSTG, (i + 2) * BK);
        asm volatile("cp.async.commit_group;\n");
        asm volatile("cp.async.wait_group 2;\n");
        __syncthreads();

        const uint32_t* As_ = As0 + (size_t)(i % NSTG) * STAGE_WORDS;
        const uint32_t* Bs_ = Bs0 + (size_t)(i % NSTG) * STAGE_WORDS;

        #pragma unroll
        for (int ks = 0; ks < 2; ks++) {
            const int k0 = ks * 8;
            uint32_t afr[4][4];
            uint32_t bfr[4][2];
            #pragma unroll
            for (int mi = 0; mi < 4; mi++) {
                int r = m_base + mi * 16 + qr;
                afr[mi][0] = As_[(k0 + qc) * LDA + r];
                afr[mi][1] = As_[(k0 + qc) * LDA + r + 8];
                afr[mi][2] = As_[(k0 + qc + 4) * LDA + r];
                afr[mi][3] = As_[(k0 + qc + 4) * LDA + r + 8];
            }
            #pragma unroll
            for (int ni = 0; ni < 4; ni++) {
                int c = n_base + ni * 8 + qr;
                bfr[ni][0] = Bs_[(k0 + qc) * LDA + c];
                bfr[ni][1] = Bs_[(k0 + qc + 4) * LDA + c];
            }
            #pragma unroll
            for (int mi = 0; mi < 4; mi++)
                #pragma unroll
                for (int ni = 0; ni < 4; ni++) {
                    asm volatile(
                        "mma.sync.aligned.m16n8k8.row.col.f32.tf32.tf32.f32 "
                        "{%0,%1,%2,%3}, {%4,%5,%6,%7}, {%8,%9}, {%0,%1,%2,%3};\n"
                        : "+f"(acc[mi][ni][0]), "+f"(acc[mi][ni][1]),
                          "+f"(acc[mi][ni][2]), "+f"(acc[mi][ni][3])
                        : "r"(afr[mi][0]), "r"(afr[mi][1]),
                          "r"(afr[mi][2]), "r"(afr[mi][3]),
                          "r"(bfr[ni][0]), "r"(bfr[ni][1]));
                }
        }
        __syncthreads();
    }

    // epilogue
    float* outb = out + (size_t)b * COUT * PP;
    const int cr = lane >> 2;
    const int cc = (lane & 3) * 2;
    #pragma unroll
    for (int mi = 0; mi < 4; mi++) {
        int row = m_base + mi * 16 + cr;
        float bv0 = bias[row];
        float bv1 = bias[row + 8];
        #pragma unroll
        for (int ni = 0; ni < 4; ni++) {
            int col = n0 + n_base + ni * 8 + cc;
            float2 v0 = make_float2(acc[mi][ni][0] + bv0, acc[mi][ni][1] + bv0);
            float2 v1 = make_float2(acc[mi][ni][2] + bv1, acc[mi][ni][3] + bv1);
            *reinterpret_cast<float2*>(outb + (size_t)row * PP + col)       = v0;
            *reinterpret_cast<float2*>(outb + (size_t)(row + 8) * PP + col) = v1;
        }
    }
}

extern "C" void kernel_launch(void* const* d_in, const int* in_sizes, int n_in,
                              void* d_out, int out_size)
{
    const float* input  = (const float*)d_in[0];
    const float* offset = (const float*)d_in[1];
    const float* mask   = (const float*)d_in[2];
    const float* weight = (const float*)d_in[3];
    const float* bias   = (const float*)d_in[4];
    float* out = (float*)d_out;

    int total = BB * KK * PP;                 // 294912
    im2col_kernel<<<(total + 255) / 256, 256>>>(input, offset, mask);
    wprep_kernel<<<(MK * COUT + 255) / 256, 256>>>(weight);

    cudaFuncSetAttribute(gemm_tf32_kernel,
                         cudaFuncAttributeMaxDynamicSharedMemorySize, SMEM_BYTES);
    dim3 grid(PP / 128, 1, BB);               // (32, 1, 8)
    gemm_tf32_kernel<<<grid, 256, SMEM_BYTES>>>(bias, out);
}